// round 14
// baseline (speedup 1.0000x reference)
#include <cuda_runtime.h>
#include <cuda_fp16.h>

// out[v,:] = coef * ( 2*x[v,:]*S1 + S2 ), S1 = sum_k x[nbr[v,k]], S2 = sum_k x[nbr[v,k]]^2
// N=100000, K=16, D=128, coef = (2/6)/16 = 1/48.
// fp16 gather route, 1 node/warp. NEW: gathers staged via cp.async.cg
// (LDGSTS) into per-warp smem — all 16 rows (32 lines) in flight from 8
// instructions with no destination-register pressure (ptxas cannot sink
// them), then consumed with conflict-free LDS.64 in R8's exact accumulation
// order (bit-identical result). Convert stays __ldcs (R9 proved load-bearing).

#define TMP_N 100000
#define TMP_D 128
#define TMP_K 16

// fp16 copy of x: [N, 32] uint2 (4 halves per uint2), 256B per row.
__device__ __align__(16) uint2 g_xh[TMP_N * TMP_D / 4];

__global__ __launch_bounds__(256) void TMP_convert_kernel(
    const float4* __restrict__ x, int n4)
{
    int i = blockIdx.x * blockDim.x + threadIdx.x;
    if (i >= n4) return;
    float4 v = __ldcs(&x[i]);   // evict-first: keep x OUT of L2 (protect xh)
    __half2 h0 = __floats2half2_rn(v.x, v.y);
    __half2 h1 = __floats2half2_rn(v.z, v.w);
    uint2 p;
    p.x = *reinterpret_cast<unsigned int*>(&h0);
    p.y = *reinterpret_cast<unsigned int*>(&h1);
    g_xh[i] = p;
}

static __device__ __forceinline__ __half2 h2bits(unsigned int u) {
    return *reinterpret_cast<__half2*>(&u);
}

__global__ __launch_bounds__(256) void TMessagePassing_11974368821731_kernel(
    const int4* __restrict__ nbr4,   // [N, 4] int4 (= [N,16] int)
    float4*     __restrict__ out,    // [N, 32] float4
    int n)
{
    // Per-warp staging buffer: 16 rows x 256B = 4KB. 8 warps -> 32KB/CTA.
    __shared__ __align__(16) unsigned char smem_buf[8][TMP_K * 256];

    int warp = (int)((blockIdx.x * blockDim.x + threadIdx.x) >> 5);
    int wic  = (int)(threadIdx.x >> 5);    // warp-in-CTA
    int lane = threadIdx.x & 31;
    if (warp >= n) return;

    const float coef = 1.0f / 48.0f;

    // 16 neighbor indices via 4 vector loads (uniform -> broadcast).
    const int4* nv = nbr4 + (long long)warp * 4;
    int idx[TMP_K];
#pragma unroll
    for (int r = 0; r < 4; r++) {
        int4 q = __ldg(&nv[r]);
        idx[4 * r + 0] = q.x; idx[4 * r + 1] = q.y;
        idx[4 * r + 2] = q.z; idx[4 * r + 3] = q.w;
    }

    // Stage all 16 rows via cp.async.cg: instruction i copies rows 2i (lanes
    // 0-15) and 2i+1 (lanes 16-31), 16B per lane. 32 lines in flight, 0 regs.
    unsigned int sbase = (unsigned int)__cvta_generic_to_shared(smem_buf[wic]);
    const char* gbase = (const char*)g_xh;
    int half16 = lane >> 4;            // which of the 2 rows this lane serves
    int off16  = (lane & 15) * 16;     // byte offset within the 256B row
#pragma unroll
    for (int i = 0; i < 8; i++) {
        int r = 2 * i + half16;
        const char* gsrc = gbase + ((long long)idx[r] * 256 + off16);
        unsigned int sdst = sbase + (unsigned)(r * 256 + off16);
        asm volatile("cp.async.cg.shared.global [%0], [%1], 16;"
                     :: "r"(sdst), "l"(gsrc));
    }
    asm volatile("cp.async.commit_group;");

    // Self row (fp16, L2-resident) while gathers are in flight.
    uint2 ps = __ldg(&g_xh[(unsigned)warp * 32u + (unsigned)lane]);

    asm volatile("cp.async.wait_group 0;");
    __syncwarp();

    const uint2* sb = (const uint2*)smem_buf[wic];   // row k at sb[k*32 + lane]

    float4 s1 = make_float4(0.f, 0.f, 0.f, 0.f);
    float4 s2 = make_float4(0.f, 0.f, 0.f, 0.f);

    // 2 runs of 8 rows; half2 accumulation within a run, fp32 flush after.
    // Same order/arithmetic as R8 -> bit-identical output.
#pragma unroll
    for (int run = 0; run < 2; run++) {
        __half2 t0, t1, q0, q1;
        {
            uint2 p = sb[(8 * run) * 32 + lane];
            __half2 a0 = h2bits(p.x), a1 = h2bits(p.y);
            t0 = a0;              t1 = a1;
            q0 = __hmul2(a0, a0); q1 = __hmul2(a1, a1);
        }
#pragma unroll
        for (int j = 1; j < 8; j++) {
            uint2 p = sb[(8 * run + j) * 32 + lane];
            __half2 a0 = h2bits(p.x), a1 = h2bits(p.y);
            t0 = __hadd2(t0, a0);     t1 = __hadd2(t1, a1);
            q0 = __hfma2(a0, a0, q0); q1 = __hfma2(a1, a1, q1);
        }
        float2 f;
        f = __half22float2(t0); s1.x += f.x; s1.y += f.y;
        f = __half22float2(t1); s1.z += f.x; s1.w += f.y;
        f = __half22float2(q0); s2.x += f.x; s2.y += f.y;
        f = __half22float2(q1); s2.z += f.x; s2.w += f.y;
    }

    float2 xv0 = __half22float2(h2bits(ps.x));
    float2 xv1 = __half22float2(h2bits(ps.y));

    float4 o;
    o.x = coef * fmaf(xv0.x + xv0.x, s1.x, s2.x);
    o.y = coef * fmaf(xv0.y + xv0.y, s1.y, s2.y);
    o.z = coef * fmaf(xv1.x + xv1.x, s1.z, s2.z);
    o.w = coef * fmaf(xv1.y + xv1.y, s1.w, s2.w);

    // Streaming store: keep out from evicting xh in L2.
    __stcs(&out[(long long)warp * 32 + lane], o);
}

extern "C" void kernel_launch(void* const* d_in, const int* in_sizes, int n_in,
                              void* d_out, int out_size)
{
    const float4* x    = (const float4*)d_in[0];
    const int4*   nbr4 = (const int4*)d_in[1];
    float4*       out  = (float4*)d_out;

    int n  = in_sizes[1] / TMP_K;      // N nodes
    int n4 = in_sizes[0] / 4;          // N*D/4 float4s

    TMP_convert_kernel<<<(n4 + 255) / 256, 256>>>(x, n4);

    int warps_per_block = 256 / 32;    // 8 nodes per block
    int blocks = (n + warps_per_block - 1) / warps_per_block;
    TMessagePassing_11974368821731_kernel<<<blocks, 256>>>(nbr4, out, n);
}

// round 15
// speedup vs baseline: 1.5103x; 1.5103x over previous
#include <cuda_runtime.h>
#include <cuda_fp16.h>

// out[v,:] = coef * sum_k ( 2*x[v]*u_k + u_k^2 )  with u_k = x[nbr[v,k]]
//          = coef * sum_k u_k * (2*x[v] + u_k)     <- single-accumulator form
// N=100000, K=16, D=128, coef = (2/6)/16 = 1/48.
// fp16 gather route, 1 node/warp (R10 = 43.5us baseline). Refactor: with
// w = 2*xv precomputed (exact in half), each row needs hadd2(w,u) + hfma2
// into ONE accumulator set -> flush halves, epilogue shrinks to 4 FMULs,
// ~8 accumulator regs freed. ~17% fewer issued instructions.

#define TMP_N 100000
#define TMP_D 128
#define TMP_K 16

// fp16 copy of x: [N, 32] uint2 (4 halves per lane).
__device__ __align__(16) uint2 g_xh[TMP_N * TMP_D / 4];

__global__ __launch_bounds__(256) void TMP_convert_kernel(
    const float4* __restrict__ x, int n4)
{
    int i = blockIdx.x * blockDim.x + threadIdx.x;
    if (i >= n4) return;
    float4 v = __ldcs(&x[i]);   // evict-first: keep x OUT of L2 (protect xh)
    __half2 h0 = __floats2half2_rn(v.x, v.y);
    __half2 h1 = __floats2half2_rn(v.z, v.w);
    uint2 p;
    p.x = *reinterpret_cast<unsigned int*>(&h0);
    p.y = *reinterpret_cast<unsigned int*>(&h1);
    g_xh[i] = p;
}

static __device__ __forceinline__ __half2 h2bits(unsigned int u) {
    return *reinterpret_cast<__half2*>(&u);
}

__global__ __launch_bounds__(256) void TMessagePassing_11974368821731_kernel(
    const int4* __restrict__ nbr4,   // [N, 4] int4 (= [N,16] int)
    float4*     __restrict__ out,    // [N, 32] float4
    int n)
{
    int warp = (int)((blockIdx.x * blockDim.x + threadIdx.x) >> 5);
    int lane = threadIdx.x & 31;
    if (warp >= n) return;

    const float coef = 1.0f / 48.0f;
    const uint2* __restrict__ xh = g_xh;

    // 16 neighbor indices via 4 vector loads (uniform -> broadcast).
    const int4* nv = nbr4 + (long long)warp * 4;
    int idx[TMP_K];
#pragma unroll
    for (int r = 0; r < 4; r++) {
        int4 q = __ldg(&nv[r]);
        idx[4 * r + 0] = q.x; idx[4 * r + 1] = q.y;
        idx[4 * r + 2] = q.z; idx[4 * r + 3] = q.w;
    }

    // Self row (fp16, L2-resident); w = 2*xv (exact: exponent bump).
    uint2 ps = __ldg(&xh[(unsigned)warp * 32u + (unsigned)lane]);
    __half2 w0 = __hadd2(h2bits(ps.x), h2bits(ps.x));
    __half2 w1 = __hadd2(h2bits(ps.y), h2bits(ps.y));

    float4 acc = make_float4(0.f, 0.f, 0.f, 0.f);

    // 2 runs of 8 gathers; per row: s = w + u; a += u*s  (half2),
    // flushed to fp32 after each run.
#pragma unroll
    for (int run = 0; run < 2; run++) {
        __half2 a0, a1;
        {
            uint2 p = __ldg(&xh[(unsigned)idx[8 * run] * 32u + (unsigned)lane]);
            __half2 u0 = h2bits(p.x), u1 = h2bits(p.y);
            a0 = __hmul2(u0, __hadd2(w0, u0));
            a1 = __hmul2(u1, __hadd2(w1, u1));
        }
#pragma unroll
        for (int j = 1; j < 8; j++) {
            uint2 p = __ldg(&xh[(unsigned)idx[8 * run + j] * 32u + (unsigned)lane]);
            __half2 u0 = h2bits(p.x), u1 = h2bits(p.y);
            a0 = __hfma2(u0, __hadd2(w0, u0), a0);
            a1 = __hfma2(u1, __hadd2(w1, u1), a1);
        }
        float2 f;
        f = __half22float2(a0); acc.x += f.x; acc.y += f.y;
        f = __half22float2(a1); acc.z += f.x; acc.w += f.y;
    }

    float4 o;
    o.x = coef * acc.x;
    o.y = coef * acc.y;
    o.z = coef * acc.z;
    o.w = coef * acc.w;

    // Streaming store: keep out from evicting xh in L2.
    __stcs(&out[(long long)warp * 32 + lane], o);
}

extern "C" void kernel_launch(void* const* d_in, const int* in_sizes, int n_in,
                              void* d_out, int out_size)
{
    const float4* x    = (const float4*)d_in[0];
    const int4*   nbr4 = (const int4*)d_in[1];
    float4*       out  = (float4*)d_out;

    int n  = in_sizes[1] / TMP_K;      // N nodes
    int n4 = in_sizes[0] / 4;          // N*D/4 float4s

    TMP_convert_kernel<<<(n4 + 255) / 256, 256>>>(x, n4);

    int warps_per_block = 256 / 32;    // 8 nodes per block
    int blocks = (n + warps_per_block - 1) / warps_per_block;
    TMessagePassing_11974368821731_kernel<<<blocks, 256>>>(nbr4, out, n);
}

// round 16
// speedup vs baseline: 1.6109x; 1.0666x over previous
#include <cuda_runtime.h>
#include <cuda_fp16.h>

// out[v,:] = coef * sum_k u_k * (2*x[v] + u_k),  u_k = x[nbr[v,k]]
// N=100000, K=16, D=128, coef = (2/6)/16 = 1/48.
// fp16 gather route, 1 node/warp, single-accumulator form (R15 win).
// R16 deltas: (a) single run of 16 with ONE fp32 flush (saves ~10 instrs);
// (b) convert coarsened x2 (two independent __ldcs per thread, MLP=2) to
// push the DRAM stream toward the bandwidth ceiling.

#define TMP_N 100000
#define TMP_D 128
#define TMP_K 16

// fp16 copy of x: [N, 32] uint2 (4 halves per lane).
__device__ __align__(16) uint2 g_xh[TMP_N * TMP_D / 4];

__global__ __launch_bounds__(256) void TMP_convert_kernel(
    const float4* __restrict__ x, int n4)
{
    int i = blockIdx.x * blockDim.x + threadIdx.x;
    int stride = gridDim.x * blockDim.x;
    int j0 = i;
    int j1 = i + stride;
    // Two independent evict-first loads in flight per thread.
    float4 v0, v1;
    bool b0 = j0 < n4, b1 = j1 < n4;
    if (b0) v0 = __ldcs(&x[j0]);
    if (b1) v1 = __ldcs(&x[j1]);
    if (b0) {
        __half2 h0 = __floats2half2_rn(v0.x, v0.y);
        __half2 h1 = __floats2half2_rn(v0.z, v0.w);
        uint2 p;
        p.x = *reinterpret_cast<unsigned int*>(&h0);
        p.y = *reinterpret_cast<unsigned int*>(&h1);
        g_xh[j0] = p;
    }
    if (b1) {
        __half2 h0 = __floats2half2_rn(v1.x, v1.y);
        __half2 h1 = __floats2half2_rn(v1.z, v1.w);
        uint2 p;
        p.x = *reinterpret_cast<unsigned int*>(&h0);
        p.y = *reinterpret_cast<unsigned int*>(&h1);
        g_xh[j1] = p;
    }
}

static __device__ __forceinline__ __half2 h2bits(unsigned int u) {
    return *reinterpret_cast<__half2*>(&u);
}

__global__ __launch_bounds__(256) void TMessagePassing_11974368821731_kernel(
    const int4* __restrict__ nbr4,   // [N, 4] int4 (= [N,16] int)
    float4*     __restrict__ out,    // [N, 32] float4
    int n)
{
    int warp = (int)((blockIdx.x * blockDim.x + threadIdx.x) >> 5);
    int lane = threadIdx.x & 31;
    if (warp >= n) return;

    const float coef = 1.0f / 48.0f;
    const uint2* __restrict__ xh = g_xh;

    // 16 neighbor indices via 4 vector loads (uniform -> broadcast).
    const int4* nv = nbr4 + (long long)warp * 4;
    int idx[TMP_K];
#pragma unroll
    for (int r = 0; r < 4; r++) {
        int4 q = __ldg(&nv[r]);
        idx[4 * r + 0] = q.x; idx[4 * r + 1] = q.y;
        idx[4 * r + 2] = q.z; idx[4 * r + 3] = q.w;
    }

    // Self row (fp16, L2-resident); w = 2*xv (exact: exponent bump).
    uint2 ps = __ldg(&xh[(unsigned)warp * 32u + (unsigned)lane]);
    __half2 w0 = __hadd2(h2bits(ps.x), h2bits(ps.x));
    __half2 w1 = __hadd2(h2bits(ps.y), h2bits(ps.y));

    // Single run of 16; per row: s = w + u; a += u*s (half2). One fp32 flush.
    __half2 a0, a1;
    {
        uint2 p = __ldg(&xh[(unsigned)idx[0] * 32u + (unsigned)lane]);
        __half2 u0 = h2bits(p.x), u1 = h2bits(p.y);
        a0 = __hmul2(u0, __hadd2(w0, u0));
        a1 = __hmul2(u1, __hadd2(w1, u1));
    }
#pragma unroll
    for (int j = 1; j < TMP_K; j++) {
        uint2 p = __ldg(&xh[(unsigned)idx[j] * 32u + (unsigned)lane]);
        __half2 u0 = h2bits(p.x), u1 = h2bits(p.y);
        a0 = __hfma2(u0, __hadd2(w0, u0), a0);
        a1 = __hfma2(u1, __hadd2(w1, u1), a1);
    }

    float2 f0 = __half22float2(a0);
    float2 f1 = __half22float2(a1);

    float4 o;
    o.x = coef * f0.x;
    o.y = coef * f0.y;
    o.z = coef * f1.x;
    o.w = coef * f1.y;

    // Streaming store: keep out from evicting xh in L2.
    __stcs(&out[(long long)warp * 32 + lane], o);
}

extern "C" void kernel_launch(void* const* d_in, const int* in_sizes, int n_in,
                              void* d_out, int out_size)
{
    const float4* x    = (const float4*)d_in[0];
    const int4*   nbr4 = (const int4*)d_in[1];
    float4*       out  = (float4*)d_out;

    int n  = in_sizes[1] / TMP_K;      // N nodes
    int n4 = in_sizes[0] / 4;          // N*D/4 float4s

    // x2 coarsened convert: each thread handles elements i and i+stride.
    int cthreads = (n4 + 1) / 2;
    TMP_convert_kernel<<<(cthreads + 255) / 256, 256>>>(x, n4);

    int warps_per_block = 256 / 32;    // 8 nodes per block
    int blocks = (n + warps_per_block - 1) / warps_per_block;
    TMessagePassing_11974368821731_kernel<<<blocks, 256>>>(nbr4, out, n);
}